// round 1
// baseline (speedup 1.0000x reference)
#include <cuda_runtime.h>
#include <math.h>

#define N   512
#define D   32
#define M   32
#define HM  64

// ---- scratch (no allocations allowed) ----
__device__ float g_h[N * D];      // node state
__device__ float g_u[N * HM];     // h@Wi^T + b*wbi
__device__ float g_v[N * HM];     // h@Wj^T + b*wbj + mp_b1
__device__ float g_msum[N * M];   // per-node message sum

// ---- packed f32x2 helpers (sm_103a FFMA2 path) ----
static __device__ __forceinline__ unsigned long long pk2(float a, float b) {
    unsigned long long r;
    asm("mov.b64 %0, {%1, %2};" : "=l"(r) : "f"(a), "f"(b));
    return r;
}
static __device__ __forceinline__ unsigned long long ffma2(unsigned long long a,
                                                           unsigned long long b,
                                                           unsigned long long c) {
    unsigned long long r;
    asm("fma.rn.f32x2 %0, %1, %2, %3;" : "=l"(r) : "l"(a), "l"(b), "l"(c));
    return r;
}
static __device__ __forceinline__ float hsum2(unsigned long long a) {
    float x, y;
    asm("mov.b64 {%0, %1}, %2;" : "=f"(x), "=f"(y) : "l"(a));
    return x + y;
}

// ---- zero h at the start of every launch (graph replays!) ----
__global__ void k_init() {
    int t = blockIdx.x * blockDim.x + threadIdx.x;
    if (t < N * D) g_h[t] = 0.f;
}

// ---- per-step: u[i,k], v[i,k]  (512 blocks x 64 threads) ----
__global__ void k_uv(const float* __restrict__ b,
                     const float* __restrict__ W1,   // (64, 67)
                     const float* __restrict__ b1) {
    int i = blockIdx.x, k = threadIdx.x;
    __shared__ float hs[D];
    if (k < D) hs[k] = g_h[i * D + k];
    __syncthreads();
    const float* row = W1 + k * 67;     // [Wi(32) | Wj(32) | wJ | wbi | wbj]
    float bi = b[i];
    float uu = bi * row[65];
    float vv = bi * row[66] + b1[k];
#pragma unroll
    for (int d = 0; d < D; d++) {
        uu = fmaf(hs[d], row[d], uu);
        vv = fmaf(hs[d], row[D + d], vv);
    }
    g_u[i * HM + k] = uu;
    g_v[i * HM + k] = vv;
}

// ---- the big one: fused edge MLP + message sum.
// grid = 512 (one block per destination j), 256 threads = 4 groups of 64.
// Group g handles i = g, g+4, g+8, ...  Thread k in a group owns m1[k]/m2[k];
// the 32-wide msg stage is split: thread k (kk=k&31, half=k>>5) does half a W3 row.
__global__ void __launch_bounds__(256)
k_msg(const float* __restrict__ J,
      const float* __restrict__ W1,
      const float* __restrict__ W2,   // (64,64)
      const float* __restrict__ b2,
      const float* __restrict__ W3,   // (32,64)
      const float* __restrict__ b3) {
    int j = blockIdx.x;
    int t = threadIdx.x;
    int g = t >> 6, k = t & 63;
    int kk = k & 31, half = k >> 5;

    __shared__ float v_s[HM], wj_s[HM];
    __shared__ float m1_s[4][HM];
    __shared__ float m2_s[4][HM];
    __shared__ float part_s[4][M];
    __shared__ float acc_s[4][M];

    if (t < HM) {
        v_s[t]  = g_v[j * HM + t];
        wj_s[t] = W1[t * 67 + 64];
    }

    // W2 row k as 32 packed f32x2 pairs (64 regs)
    unsigned long long w2p[32];
    {
        const float4* W2r = reinterpret_cast<const float4*>(W2 + k * HM);
#pragma unroll
        for (int c = 0; c < 16; c++) {
            float4 f = W2r[c];
            w2p[2 * c]     = pk2(f.x, f.y);
            w2p[2 * c + 1] = pk2(f.z, f.w);
        }
    }
    // half of W3 row kk as 16 packed pairs (32 regs)
    unsigned long long w3p[16];
    {
        const float4* W3r = reinterpret_cast<const float4*>(W3 + kk * HM + half * 32);
#pragma unroll
        for (int c = 0; c < 8; c++) {
            float4 f = W3r[c];
            w3p[2 * c]     = pk2(f.x, f.y);
            w3p[2 * c + 1] = pk2(f.z, f.w);
        }
    }
    float b2r = b2[k];
    float b3r = (half == 0) ? b3[kk] : 0.f;
    float acc = 0.f;
    __syncthreads();

    const float4* m1v = reinterpret_cast<const float4*>(m1_s[g]);
    const float4* m2v = reinterpret_cast<const float4*>(m2_s[g] + half * 32);

    for (int i = g; i < N; i += 4) {
        // phase A: m1[k] = relu(u[i,k] + v[j,k] + J[i,j]*wJ[k])
        float Jij = __ldg(J + (size_t)i * N + j);
        float pre = g_u[i * HM + k] + v_s[k] + Jij * wj_s[k];
        m1_s[g][k] = fmaxf(pre, 0.f);
        __syncthreads();                       // S1

        // phase B: m2[k] = relu(W2[k,:]·m1 + b2[k])   (32 FFMA2 = 64 MACs)
        unsigned long long a2 = 0ull;
#pragma unroll
        for (int c = 0; c < 16; c++) {
            float4 f = m1v[c];
            a2 = ffma2(pk2(f.x, f.y), w2p[2 * c],     a2);
            a2 = ffma2(pk2(f.z, f.w), w2p[2 * c + 1], a2);
        }
        m2_s[g][k] = fmaxf(hsum2(a2) + b2r, 0.f);
        __syncthreads();                       // S2

        // phase C: msg[kk] = relu(W3[kk,:]·m2 + b3[kk]), split over two halves
        unsigned long long a3 = 0ull;
#pragma unroll
        for (int c = 0; c < 8; c++) {
            float4 f = m2v[c];
            a3 = ffma2(pk2(f.x, f.y), w3p[2 * c],     a3);
            a3 = ffma2(pk2(f.z, f.w), w3p[2 * c + 1], a3);
        }
        float p = hsum2(a3);
        if (half) part_s[g][kk] = p;
        __syncthreads();                       // S3
        if (!half) acc += fmaxf(p + part_s[g][kk] + b3r, 0.f);
        // part_s read(after S3) vs next write(after next S2): protected by S1,S2
    }

    if (!half) acc_s[g][kk] = acc;
    __syncthreads();
    if (t < M)
        g_msum[j * M + t] = acc_s[0][t] + acc_s[1][t] + acc_s[2][t] + acc_s[3][t];
}

// ---- GRU update (in-place safe: block j touches only row j) ----
__global__ void k_gru(const float* __restrict__ Wih,   // (96, 64)
                      const float* __restrict__ Whh,   // (96, 32)
                      const float* __restrict__ bih,
                      const float* __restrict__ bhh) {
    int jn = blockIdx.x;
    int q = threadIdx.x;                 // 96 threads
    __shared__ float x[2 * D];
    __shared__ float gi_s[3 * D], gh_s[3 * D];
    if (q < D) x[q] = g_h[jn * D + q];
    else if (q < 2 * D) x[q] = g_msum[jn * M + (q - D)];
    __syncthreads();
    float gi = bih[q], gh = bhh[q];
    const float* wi = Wih + q * (2 * D);
    const float* wh = Whh + q * D;
#pragma unroll
    for (int c = 0; c < 2 * D; c++) gi = fmaf(x[c], wi[c], gi);
#pragma unroll
    for (int c = 0; c < D; c++)     gh = fmaf(x[c], wh[c], gh);
    gi_s[q] = gi; gh_s[q] = gh;
    __syncthreads();
    if (q < D) {
        float r  = 1.f / (1.f + expf(-(gi_s[q]        + gh_s[q])));
        float z  = 1.f / (1.f + expf(-(gi_s[D + q]    + gh_s[D + q])));
        float ng = tanhf(gi_s[2 * D + q] + r * gh_s[2 * D + q]);
        g_h[jn * D + q] = (1.f - z) * ng + z * x[q];
    }
}

// ---- readout MLP + sigmoid ----
__global__ void k_readout(const float* __restrict__ W1, const float* __restrict__ b1,
                          const float* __restrict__ W2, const float* __restrict__ b2,
                          const float* __restrict__ W3, const float* __restrict__ b3,
                          float* __restrict__ out) {
    int jn = blockIdx.x;
    int k = threadIdx.x;                 // 64 threads
    __shared__ float hs[D], y1[HM], y2[HM];
    if (k < D) hs[k] = g_h[jn * D + k];
    __syncthreads();
    float a = b1[k];
    const float* w1 = W1 + k * D;
#pragma unroll
    for (int c = 0; c < D; c++) a = fmaf(hs[c], w1[c], a);
    y1[k] = fmaxf(a, 0.f);
    __syncthreads();
    float a2 = b2[k];
    const float* w2 = W2 + k * HM;
#pragma unroll
    for (int c = 0; c < HM; c++) a2 = fmaf(y1[c], w2[c], a2);
    y2[k] = fmaxf(a2, 0.f);
    __syncthreads();
    if (k < 2) {
        float a3 = b3[k];
        const float* w3 = W3 + k * HM;
#pragma unroll
        for (int c = 0; c < HM; c++) a3 = fmaf(y2[c], w3[c], a3);
        a3 = fmaxf(a3, 0.f);
        out[jn * 2 + k] = 1.f / (1.f + expf(-a3));
    }
}

extern "C" void kernel_launch(void* const* d_in, const int* in_sizes, int n_in,
                              void* d_out, int out_size) {
    const float* J   = (const float*)d_in[0];
    const float* b   = (const float*)d_in[1];
    const float* W1  = (const float*)d_in[2];
    const float* b1  = (const float*)d_in[3];
    const float* W2  = (const float*)d_in[4];
    const float* b2  = (const float*)d_in[5];
    const float* W3  = (const float*)d_in[6];
    const float* b3  = (const float*)d_in[7];
    const float* Wih = (const float*)d_in[8];
    const float* Whh = (const float*)d_in[9];
    const float* bih = (const float*)d_in[10];
    const float* bhh = (const float*)d_in[11];
    const float* rW1 = (const float*)d_in[12];
    const float* rb1 = (const float*)d_in[13];
    const float* rW2 = (const float*)d_in[14];
    const float* rb2 = (const float*)d_in[15];
    const float* rW3 = (const float*)d_in[16];
    const float* rb3 = (const float*)d_in[17];
    float* out = (float*)d_out;

    k_init<<<16, 1024>>>();
    for (int s = 0; s < 5; s++) {
        k_uv<<<N, HM>>>(b, W1, b1);
        k_msg<<<N, 256>>>(J, W1, W2, b2, W3, b3);
        k_gru<<<N, 96>>>(Wih, Whh, bih, bhh);
    }
    k_readout<<<N, HM>>>(rW1, rb1, rW2, rb2, rW3, rb3, out);
}

// round 3
// speedup vs baseline: 4.8087x; 4.8087x over previous
#include <cuda_runtime.h>
#include <math.h>
#include <stdint.h>

#define NN   512
#define DD   32

// ---------------- device scratch ----------------
__device__ float g_h[NN * DD];
__device__ float g_u[NN * 64];
__device__ float g_v[NN * 64];
__device__ float g_msum[NN * DD];
__device__ float g_Jt[NN * NN];

// ---------------- helpers ----------------
static __device__ __forceinline__ uint32_t smem_u32(const void* p) {
    uint32_t a;
    asm("{ .reg .u64 t; cvta.to.shared.u64 t, %1; cvt.u32.u64 %0, t; }"
        : "=r"(a) : "l"(p));
    return a;
}
// pack (lo,hi) -> bf16x2 (lo in low half)
static __device__ __forceinline__ uint32_t cvt2(float lo, float hi) {
    uint32_t r;
    asm("cvt.rn.bf16x2.f32 %0, %1, %2;" : "=r"(r) : "f"(hi), "f"(lo));
    return r;
}
#define SW128(o) ((o) ^ ((((uint32_t)(o)) >> 3) & 0x70u))

static __device__ __forceinline__ void ldm4(uint32_t* r, uint32_t addr) {
    asm volatile("ldmatrix.sync.aligned.m8n8.x4.shared.b16 {%0,%1,%2,%3},[%4];"
                 : "=r"(r[0]), "=r"(r[1]), "=r"(r[2]), "=r"(r[3]) : "r"(addr));
}
static __device__ __forceinline__ void mma16816(float* d, const uint32_t* a,
                                                uint32_t b0, uint32_t b1) {
    asm volatile(
        "mma.sync.aligned.m16n8k16.row.col.f32.bf16.bf16.f32 "
        "{%0,%1,%2,%3}, {%4,%5,%6,%7}, {%8,%9}, {%0,%1,%2,%3};"
        : "+f"(d[0]), "+f"(d[1]), "+f"(d[2]), "+f"(d[3])
        : "r"(a[0]), "r"(a[1]), "r"(a[2]), "r"(a[3]), "r"(b0), "r"(b1));
}

// ---------------- init ----------------
__global__ void k_init() {
    int t = blockIdx.x * blockDim.x + threadIdx.x;
    if (t < NN * DD) g_h[t] = 0.f;
}

// ---------------- transpose J ----------------
__global__ void k_tr(const float* __restrict__ J) {
    __shared__ float tile[32][33];
    int bx = blockIdx.x * 32, by = blockIdx.y * 32;
    int tx = threadIdx.x, ty = threadIdx.y;
    for (int yy = ty; yy < 32; yy += 8)
        tile[yy][tx] = J[(by + yy) * NN + bx + tx];
    __syncthreads();
    for (int yy = ty; yy < 32; yy += 8)
        g_Jt[(size_t)(bx + yy) * NN + by + tx] = tile[tx][yy];
}

// ---------------- u/v precompute ----------------
__global__ void __launch_bounds__(256) k_uv(const float* __restrict__ b,
                                            const float* __restrict__ W1,  // (64,67)
                                            const float* __restrict__ b1) {
    __shared__ float W1s[64][69];
    __shared__ float hs[8][32];
    __shared__ float bv[8];
    int t = threadIdx.x;
    int n0 = blockIdx.x * 8;
    for (int idx = t; idx < 64 * 67; idx += 256)
        W1s[idx / 67][idx % 67] = W1[idx];
    {
        int nl = t >> 5, c = t & 31;
        hs[nl][c] = g_h[(n0 + nl) * DD + c];
    }
    if (t < 8) bv[t] = b[n0 + t];
    __syncthreads();
    int k = t & 63;
    int nlb = t >> 6;
    float b1k = b1[k];
#pragma unroll
    for (int rep = 0; rep < 2; rep++) {
        int nl = nlb + rep * 4;
        float uu = bv[nl] * W1s[k][65];
        float vv = bv[nl] * W1s[k][66] + b1k;
#pragma unroll
        for (int d = 0; d < DD; d++) {
            uu = fmaf(hs[nl][d], W1s[k][d], uu);
            vv = fmaf(hs[nl][d], W1s[k][DD + d], vv);
        }
        g_u[(n0 + nl) * 64 + k] = uu;
        g_v[(n0 + nl) * 64 + k] = vv;
    }
}

// ---------------- edge MLP + message sum via mma.sync (HMMA bf16) ----------------
// 512 blocks (one per j), 128 threads = 4 warps; warp w owns rows [32w, 32w+32)
// of each 128-row i-tile as two m16 tiles.
__global__ void __launch_bounds__(128)
k_msg(const float* __restrict__ W1,
      const float* __restrict__ W2,   // (64,64)
      const float* __restrict__ b2,
      const float* __restrict__ W3,   // (32,64)
      const float* __restrict__ b3) {
    __shared__ __align__(1024) uint8_t Atile[128 * 128];  // bf16 128x64, SW128
    __shared__ uint32_t W2s[64][36];   // bf16x2 words, rows padded to 36 words
    __shared__ uint32_t W3s[32][36];
    __shared__ float v_s[64], wj_s[64], b2_s[64], b3_s[32];
    __shared__ float Jcol[128];
    __shared__ float wpart[4][32];

    int t = threadIdx.x;
    int lane = t & 31, wid = t >> 5;
    int j = blockIdx.x;
    uint32_t abase = smem_u32(Atile);

    // stage weights as bf16x2
    for (int idx = t; idx < 2048; idx += 128) {       // W2: 64 rows x 32 words
        int r = idx >> 5, w = idx & 31;
        float2 p = *(const float2*)(W2 + r * 64 + 2 * w);
        W2s[r][w] = cvt2(p.x, p.y);
    }
    for (int idx = t; idx < 1024; idx += 128) {       // W3: 32 rows x 32 words
        int r = idx >> 5, w = idx & 31;
        float2 p = *(const float2*)(W3 + r * 64 + 2 * w);
        W3s[r][w] = cvt2(p.x, p.y);
    }
    if (t < 64) {
        v_s[t]  = g_v[j * 64 + t];
        wj_s[t] = W1[t * 67 + 64];
        b2_s[t] = b2[t];
    }
    if (t < 32) b3_s[t] = b3[t];
    __syncthreads();

    // per-thread bias registers (fragment column mapping)
    float b2r[8][2], b3r[4][2];
#pragma unroll
    for (int nt = 0; nt < 8; nt++) {
        b2r[nt][0] = b2_s[nt * 8 + (lane & 3) * 2];
        b2r[nt][1] = b2_s[nt * 8 + (lane & 3) * 2 + 1];
    }
#pragma unroll
    for (int nt = 0; nt < 4; nt++) {
        b3r[nt][0] = b3_s[nt * 8 + (lane & 3) * 2];
        b3r[nt][1] = b3_s[nt * 8 + (lane & 3) * 2 + 1];
    }
    float acc[4][2];
#pragma unroll
    for (int nt = 0; nt < 4; nt++) acc[nt][0] = acc[nt][1] = 0.f;

    for (int i0 = 0; i0 < NN; i0 += 128) {
        // ---- build m1 tile (all 128 threads) ----
        Jcol[t] = g_Jt[(size_t)j * NN + i0 + t];
        __syncthreads();
#pragma unroll 4
        for (int q = 0; q < 16; q++) {
            int idx4 = t + 128 * q;
            int r = idx4 >> 4, c4 = (idx4 & 15) * 4;
            float4 u4 = *(const float4*)(g_u + (i0 + r) * 64 + c4);
            float Jv = Jcol[r];
            float m0 = fmaxf(fmaf(Jv, wj_s[c4 + 0], u4.x + v_s[c4 + 0]), 0.f);
            float m1 = fmaxf(fmaf(Jv, wj_s[c4 + 1], u4.y + v_s[c4 + 1]), 0.f);
            float m2 = fmaxf(fmaf(Jv, wj_s[c4 + 2], u4.z + v_s[c4 + 2]), 0.f);
            float m3 = fmaxf(fmaf(Jv, wj_s[c4 + 3], u4.w + v_s[c4 + 3]), 0.f);
            *(uint2*)(Atile + SW128(r * 128 + c4 * 2)) =
                make_uint2(cvt2(m0, m1), cvt2(m2, m3));
        }
        __syncthreads();

        // ---- MMA1: 32 rows/warp x 64 cols, K=64 ----
        float d1[2][8][4];
#pragma unroll
        for (int mt = 0; mt < 2; mt++)
#pragma unroll
            for (int nt = 0; nt < 8; nt++)
#pragma unroll
                for (int c = 0; c < 4; c++) d1[mt][nt][c] = 0.f;
#pragma unroll
        for (int kt = 0; kt < 4; kt++) {
            uint32_t a[2][4];
#pragma unroll
            for (int mt = 0; mt < 2; mt++) {
                int row = wid * 32 + mt * 16 + (lane & 15);
                ldm4(a[mt], abase + SW128(row * 128 + kt * 32 + (lane >> 4) * 16));
            }
#pragma unroll
            for (int nt = 0; nt < 8; nt++) {
                uint32_t b0 = W2s[nt * 8 + (lane >> 2)][kt * 8 + (lane & 3)];
                uint32_t b1 = W2s[nt * 8 + (lane >> 2)][kt * 8 + (lane & 3) + 4];
                mma16816(d1[0][nt], a[0], b0, b1);
                mma16816(d1[1][nt], a[1], b0, b1);
            }
        }
        __syncwarp();
        // ---- epi1: relu+b2 -> bf16 back into Atile (own rows only) ----
#pragma unroll
        for (int mt = 0; mt < 2; mt++) {
            int row = wid * 32 + mt * 16 + (lane >> 2);
#pragma unroll
            for (int nt = 0; nt < 8; nt++) {
                int cb = (nt * 8 + (lane & 3) * 2) * 2;     // byte col
                float x0 = fmaxf(d1[mt][nt][0] + b2r[nt][0], 0.f);
                float x1 = fmaxf(d1[mt][nt][1] + b2r[nt][1], 0.f);
                float x2 = fmaxf(d1[mt][nt][2] + b2r[nt][0], 0.f);
                float x3 = fmaxf(d1[mt][nt][3] + b2r[nt][1], 0.f);
                *(uint32_t*)(Atile + SW128(row * 128 + cb))       = cvt2(x0, x1);
                *(uint32_t*)(Atile + SW128((row + 8) * 128 + cb)) = cvt2(x2, x3);
            }
        }
        __syncwarp();

        // ---- MMA2: m2 @ W3^T (N=32) ----
        float d2[2][4][4];
#pragma unroll
        for (int mt = 0; mt < 2; mt++)
#pragma unroll
            for (int nt = 0; nt < 4; nt++)
#pragma unroll
                for (int c = 0; c < 4; c++) d2[mt][nt][c] = 0.f;
#pragma unroll
        for (int kt = 0; kt < 4; kt++) {
            uint32_t a[2][4];
#pragma unroll
            for (int mt = 0; mt < 2; mt++) {
                int row = wid * 32 + mt * 16 + (lane & 15);
                ldm4(a[mt], abase + SW128(row * 128 + kt * 32 + (lane >> 4) * 16));
            }
#pragma unroll
            for (int nt = 0; nt < 4; nt++) {
                uint32_t b0 = W3s[nt * 8 + (lane >> 2)][kt * 8 + (lane & 3)];
                uint32_t b1 = W3s[nt * 8 + (lane >> 2)][kt * 8 + (lane & 3) + 4];
                mma16816(d2[0][nt], a[0], b0, b1);
                mma16816(d2[1][nt], a[1], b0, b1);
            }
        }
        // ---- epi2: relu+b3, accumulate column sums ----
#pragma unroll
        for (int mt = 0; mt < 2; mt++)
#pragma unroll
            for (int nt = 0; nt < 4; nt++) {
                acc[nt][0] += fmaxf(d2[mt][nt][0] + b3r[nt][0], 0.f)
                            + fmaxf(d2[mt][nt][2] + b3r[nt][0], 0.f);
                acc[nt][1] += fmaxf(d2[mt][nt][1] + b3r[nt][1], 0.f)
                            + fmaxf(d2[mt][nt][3] + b3r[nt][1], 0.f);
            }
        __syncthreads();   // before next tile's build overwrites Atile
    }

    // ---- reduction: lanes sharing (lane&3) hold same columns ----
#pragma unroll
    for (int nt = 0; nt < 4; nt++)
#pragma unroll
        for (int c = 0; c < 2; c++) {
            float v = acc[nt][c];
            v += __shfl_xor_sync(0xFFFFFFFFu, v, 4);
            v += __shfl_xor_sync(0xFFFFFFFFu, v, 8);
            v += __shfl_xor_sync(0xFFFFFFFFu, v, 16);
            acc[nt][c] = v;
        }
    if (lane < 4) {
#pragma unroll
        for (int nt = 0; nt < 4; nt++) {
            wpart[wid][nt * 8 + lane * 2]     = acc[nt][0];
            wpart[wid][nt * 8 + lane * 2 + 1] = acc[nt][1];
        }
    }
    __syncthreads();
    if (t < 32)
        g_msum[j * 32 + t] = wpart[0][t] + wpart[1][t] + wpart[2][t] + wpart[3][t];
}

// ---------------- GRU ----------------
__global__ void __launch_bounds__(384) k_gru(const float* __restrict__ Wih,  // (96,64)
                                             const float* __restrict__ Whh,  // (96,32)
                                             const float* __restrict__ bih,
                                             const float* __restrict__ bhh) {
    __shared__ float Wih_s[96][65];
    __shared__ float Whh_s[96][33];
    __shared__ float x_s[4][64];
    __shared__ float gi_s[4][96], gh_s[4][96];
    int t = threadIdx.x;
    int n0 = blockIdx.x * 4;
    for (int idx = t; idx < 96 * 64; idx += 384) Wih_s[idx >> 6][idx & 63] = Wih[idx];
    for (int idx = t; idx < 96 * 32; idx += 384) Whh_s[idx >> 5][idx & 31] = Whh[idx];
    if (t < 256) {
        int nl = t >> 6, c = t & 63;
        x_s[nl][c] = (c < 32) ? g_h[(n0 + nl) * DD + c]
                              : g_msum[(n0 + nl) * DD + (c - 32)];
    }
    __syncthreads();
    int nl = t / 96, q = t % 96;
    float gi = bih[q], gh = bhh[q];
#pragma unroll
    for (int c = 0; c < 64; c++) gi = fmaf(x_s[nl][c], Wih_s[q][c], gi);
#pragma unroll
    for (int c = 0; c < 32; c++) gh = fmaf(x_s[nl][c], Whh_s[q][c], gh);
    gi_s[nl][q] = gi; gh_s[nl][q] = gh;
    __syncthreads();
    if (q < 32) {
        float r  = 1.f / (1.f + expf(-(gi_s[nl][q]      + gh_s[nl][q])));
        float z  = 1.f / (1.f + expf(-(gi_s[nl][32 + q] + gh_s[nl][32 + q])));
        float ng = tanhf(gi_s[nl][64 + q] + r * gh_s[nl][64 + q]);
        g_h[(n0 + nl) * DD + q] = (1.f - z) * ng + z * x_s[nl][q];
    }
}

// ---------------- readout ----------------
__global__ void k_readout(const float* __restrict__ W1, const float* __restrict__ b1,
                          const float* __restrict__ W2, const float* __restrict__ b2,
                          const float* __restrict__ W3, const float* __restrict__ b3,
                          float* __restrict__ out) {
    int jn = blockIdx.x;
    int k = threadIdx.x;                 // 64 threads
    __shared__ float hs[DD], y1[64], y2[64];
    if (k < DD) hs[k] = g_h[jn * DD + k];
    __syncthreads();
    float a = b1[k];
    const float* w1 = W1 + k * DD;
#pragma unroll
    for (int c = 0; c < DD; c++) a = fmaf(hs[c], w1[c], a);
    y1[k] = fmaxf(a, 0.f);
    __syncthreads();
    float a2 = b2[k];
    const float* w2 = W2 + k * 64;
#pragma unroll
    for (int c = 0; c < 64; c++) a2 = fmaf(y1[c], w2[c], a2);
    y2[k] = fmaxf(a2, 0.f);
    __syncthreads();
    if (k < 2) {
        float a3 = b3[k];
        const float* w3 = W3 + k * 64;
#pragma unroll
        for (int c = 0; c < 64; c++) a3 = fmaf(y2[c], w3[c], a3);
        a3 = fmaxf(a3, 0.f);
        out[jn * 2 + k] = 1.f / (1.f + expf(-a3));
    }
}

extern "C" void kernel_launch(void* const* d_in, const int* in_sizes, int n_in,
                              void* d_out, int out_size) {
    const float* J   = (const float*)d_in[0];
    const float* b   = (const float*)d_in[1];
    const float* W1  = (const float*)d_in[2];
    const float* b1  = (const float*)d_in[3];
    const float* W2  = (const float*)d_in[4];
    const float* b2  = (const float*)d_in[5];
    const float* W3  = (const float*)d_in[6];
    const float* b3  = (const float*)d_in[7];
    const float* Wih = (const float*)d_in[8];
    const float* Whh = (const float*)d_in[9];
    const float* bih = (const float*)d_in[10];
    const float* bhh = (const float*)d_in[11];
    const float* rW1 = (const float*)d_in[12];
    const float* rb1 = (const float*)d_in[13];
    const float* rW2 = (const float*)d_in[14];
    const float* rb2 = (const float*)d_in[15];
    const float* rW3 = (const float*)d_in[16];
    const float* rb3 = (const float*)d_in[17];
    float* out = (float*)d_out;

    k_init<<<16, 1024>>>();
    k_tr<<<dim3(16, 16), dim3(32, 8)>>>(J);
    for (int s = 0; s < 5; s++) {
        k_uv<<<64, 256>>>(b, W1, b1);
        k_msg<<<NN, 128>>>(W1, W2, b2, W3, b3);
        k_gru<<<128, 384>>>(Wih, Whh, bih, bhh);
    }
    k_readout<<<NN, 64>>>(rW1, rb1, rW2, rb2, rW3, rb3, out);
}

// round 5
// speedup vs baseline: 5.5160x; 1.1471x over previous
#include <cuda_runtime.h>
#include <math.h>
#include <stdint.h>

#define NN   512
#define DD   32

// ---------------- device scratch ----------------
__device__ float g_h[NN * DD];
__device__ float g_u[NN * 64];
__device__ float g_v[NN * 64];
__device__ float g_msum[NN * DD];
__device__ float g_Jt[NN * NN];

// ---------------- helpers ----------------
static __device__ __forceinline__ uint32_t smem_u32(const void* p) {
    uint32_t a;
    asm("{ .reg .u64 t; cvta.to.shared.u64 t, %1; cvt.u32.u64 %0, t; }"
        : "=r"(a) : "l"(p));
    return a;
}
static __device__ __forceinline__ uint32_t cvt2(float lo, float hi) {
    uint32_t r;
    asm("cvt.rn.bf16x2.f32 %0, %1, %2;" : "=r"(r) : "f"(hi), "f"(lo));
    return r;
}
#define SW128(o) ((o) ^ ((((uint32_t)(o)) >> 3) & 0x70u))

static __device__ __forceinline__ void ldm4(uint32_t* r, uint32_t addr) {
    asm volatile("ldmatrix.sync.aligned.m8n8.x4.shared.b16 {%0,%1,%2,%3},[%4];"
                 : "=r"(r[0]), "=r"(r[1]), "=r"(r[2]), "=r"(r[3]) : "r"(addr));
}
static __device__ __forceinline__ void mma16816(float* d, const uint32_t* a,
                                                uint32_t b0, uint32_t b1) {
    asm volatile(
        "mma.sync.aligned.m16n8k16.row.col.f32.bf16.bf16.f32 "
        "{%0,%1,%2,%3}, {%4,%5,%6,%7}, {%8,%9}, {%0,%1,%2,%3};"
        : "+f"(d[0]), "+f"(d[1]), "+f"(d[2]), "+f"(d[3])
        : "r"(a[0]), "r"(a[1]), "r"(a[2]), "r"(a[3]), "r"(b0), "r"(b1));
}
static __device__ __forceinline__ void mbar_init(uint32_t a, uint32_t cnt) {
    asm volatile("mbarrier.init.shared.b64 [%0], %1;" :: "r"(a), "r"(cnt) : "memory");
}
static __device__ __forceinline__ void mbar_arrive(uint32_t a) {
    asm volatile("mbarrier.arrive.shared.b64 _, [%0];" :: "r"(a) : "memory");
}
static __device__ __forceinline__ void mbar_wait(uint32_t a, uint32_t parity) {
    asm volatile(
        "{\n .reg .pred P;\n"
        "W%=: mbarrier.try_wait.parity.shared.b64 P, [%0], %1;\n"
        " @!P bra W%=;\n}"
        :: "r"(a), "r"(parity) : "memory");
}

// ---------------- init ----------------
__global__ void k_init() {
    int t = blockIdx.x * blockDim.x + threadIdx.x;
    if (t < NN * DD) g_h[t] = 0.f;
}

// ---------------- transpose J ----------------
__global__ void k_tr(const float* __restrict__ J) {
    __shared__ float tile[32][33];
    int bx = blockIdx.x * 32, by = blockIdx.y * 32;
    int tx = threadIdx.x, ty = threadIdx.y;
    for (int yy = ty; yy < 32; yy += 8)
        tile[yy][tx] = J[(by + yy) * NN + bx + tx];
    __syncthreads();
    for (int yy = ty; yy < 32; yy += 8)
        g_Jt[(size_t)(bx + yy) * NN + by + tx] = tile[tx][yy];
}

// ---------------- u/v precompute ----------------
__global__ void __launch_bounds__(256) k_uv(const float* __restrict__ b,
                                            const float* __restrict__ W1,  // (64,67)
                                            const float* __restrict__ b1) {
    __shared__ float W1s[64][69];
    __shared__ float hs[8][32];
    __shared__ float bv[8];
    int t = threadIdx.x;
    int n0 = blockIdx.x * 8;
    for (int idx = t; idx < 64 * 67; idx += 256)
        W1s[idx / 67][idx % 67] = W1[idx];
    {
        int nl = t >> 5, c = t & 31;
        hs[nl][c] = g_h[(n0 + nl) * DD + c];
    }
    if (t < 8) bv[t] = b[n0 + t];
    __syncthreads();
    int k = t & 63;
    int nlb = t >> 6;
    float b1k = b1[k];
#pragma unroll
    for (int rep = 0; rep < 2; rep++) {
        int nl = nlb + rep * 4;
        float uu = bv[nl] * W1s[k][65];
        float vv = bv[nl] * W1s[k][66] + b1k;
#pragma unroll
        for (int d = 0; d < DD; d++) {
            uu = fmaf(hs[nl][d], W1s[k][d], uu);
            vv = fmaf(hs[nl][d], W1s[k][DD + d], vv);
        }
        g_u[(n0 + nl) * 64 + k] = uu;
        g_v[(n0 + nl) * 64 + k] = vv;
    }
}

// ---------------- edge MLP + message sum: warp-specialized producer/consumer ----
// 512 blocks (one per j), 256 threads: warps 0-3 = consumers (HMMA + epilogues),
// warps 4-7 = producers (build m1 tiles). 2-stage smem ring, mbarrier paced.
__global__ void __launch_bounds__(256)
k_msg(const float* __restrict__ W1,
      const float* __restrict__ W2,   // (64,64)
      const float* __restrict__ b2,
      const float* __restrict__ W3,   // (32,64)
      const float* __restrict__ b3) {
    __shared__ uint8_t Atile[2][128 * 128];   // two 128x64 bf16 tiles, SW128
    __shared__ uint32_t W2s[64][36];
    __shared__ uint32_t W3s[32][36];
    __shared__ float v_s[64], wj_s[64], b2_s[64], b3_s[32];
    __shared__ float Jc[2][128];
    __shared__ float wpart[4][32];
    __shared__ __align__(8) unsigned long long mbar_mem[4]; // full0 full1 empty0 empty1

    int t = threadIdx.x;
    int lane = t & 31, wid = t >> 5;
    int j = blockIdx.x;
    uint32_t mb = smem_u32(mbar_mem);
    uint32_t full0 = mb, full1 = mb + 8, empty0 = mb + 16, empty1 = mb + 24;

    // ---- stage weights (all 256 threads) ----
    for (int idx = t; idx < 2048; idx += 256) {
        int r = idx >> 5, w = idx & 31;
        float2 p = *(const float2*)(W2 + r * 64 + 2 * w);
        W2s[r][w] = cvt2(p.x, p.y);
    }
    for (int idx = t; idx < 1024; idx += 256) {
        int r = idx >> 5, w = idx & 31;
        float2 p = *(const float2*)(W3 + r * 64 + 2 * w);
        W3s[r][w] = cvt2(p.x, p.y);
    }
    if (t < 64) {
        v_s[t]  = g_v[j * 64 + t];
        wj_s[t] = W1[t * 67 + 64];
        b2_s[t] = b2[t];
    }
    if (t < 32) b3_s[t] = b3[t];
    if (t == 0) {
        mbar_init(full0, 128); mbar_init(full1, 128);
        mbar_init(empty0, 128); mbar_init(empty1, 128);
    }
    __syncthreads();

    if (wid < 4) {
        // =================== CONSUMER ===================
        float b2r[8][2], b3r[4][2];
#pragma unroll
        for (int nt = 0; nt < 8; nt++) {
            b2r[nt][0] = b2_s[nt * 8 + (lane & 3) * 2];
            b2r[nt][1] = b2_s[nt * 8 + (lane & 3) * 2 + 1];
        }
#pragma unroll
        for (int nt = 0; nt < 4; nt++) {
            b3r[nt][0] = b3_s[nt * 8 + (lane & 3) * 2];
            b3r[nt][1] = b3_s[nt * 8 + (lane & 3) * 2 + 1];
        }
        float acc[4][2];
#pragma unroll
        for (int nt = 0; nt < 4; nt++) acc[nt][0] = acc[nt][1] = 0.f;

#pragma unroll 1
        for (int tt = 0; tt < 4; tt++) {
            int s = tt & 1;
            uint32_t fullb = s ? full1 : full0;
            uint32_t emptyb = s ? empty1 : empty0;
            uint32_t abase = smem_u32(Atile[s]);
            mbar_wait(fullb, (tt >> 1) & 1);

            // MMA1: rows [wid*32, wid*32+32), cols 64, K=64
            float d1[2][8][4];
#pragma unroll
            for (int mt = 0; mt < 2; mt++)
#pragma unroll
                for (int nt = 0; nt < 8; nt++)
#pragma unroll
                    for (int c = 0; c < 4; c++) d1[mt][nt][c] = 0.f;
#pragma unroll
            for (int kt = 0; kt < 4; kt++) {
                uint32_t a[2][4];
#pragma unroll
                for (int mt = 0; mt < 2; mt++) {
                    int row = wid * 32 + mt * 16 + (lane & 15);
                    ldm4(a[mt], abase + SW128(row * 128 + kt * 32 + (lane >> 4) * 16));
                }
#pragma unroll
                for (int nt = 0; nt < 8; nt++) {
                    uint32_t b0 = W2s[nt * 8 + (lane >> 2)][kt * 8 + (lane & 3)];
                    uint32_t b1 = W2s[nt * 8 + (lane >> 2)][kt * 8 + (lane & 3) + 4];
                    mma16816(d1[0][nt], a[0], b0, b1);
                    mma16816(d1[1][nt], a[1], b0, b1);
                }
            }
            __syncwarp();
            // epi1: relu+b2 -> bf16, in place (own rows only)
#pragma unroll
            for (int mt = 0; mt < 2; mt++) {
                int row = wid * 32 + mt * 16 + (lane >> 2);
#pragma unroll
                for (int nt = 0; nt < 8; nt++) {
                    int cb = (nt * 8 + (lane & 3) * 2) * 2;
                    float x0 = fmaxf(d1[mt][nt][0] + b2r[nt][0], 0.f);
                    float x1 = fmaxf(d1[mt][nt][1] + b2r[nt][1], 0.f);
                    float x2 = fmaxf(d1[mt][nt][2] + b2r[nt][0], 0.f);
                    float x3 = fmaxf(d1[mt][nt][3] + b2r[nt][1], 0.f);
                    *(uint32_t*)(Atile[s] + SW128(row * 128 + cb))       = cvt2(x0, x1);
                    *(uint32_t*)(Atile[s] + SW128((row + 8) * 128 + cb)) = cvt2(x2, x3);
                }
            }
            __syncwarp();
            // MMA2: m2 @ W3^T (N=32)
            float d2[2][4][4];
#pragma unroll
            for (int mt = 0; mt < 2; mt++)
#pragma unroll
                for (int nt = 0; nt < 4; nt++)
#pragma unroll
                    for (int c = 0; c < 4; c++) d2[mt][nt][c] = 0.f;
#pragma unroll
            for (int kt = 0; kt < 4; kt++) {
                uint32_t a[2][4];
#pragma unroll
                for (int mt = 0; mt < 2; mt++) {
                    int row = wid * 32 + mt * 16 + (lane & 15);
                    ldm4(a[mt], abase + SW128(row * 128 + kt * 32 + (lane >> 4) * 16));
                }
#pragma unroll
                for (int nt = 0; nt < 4; nt++) {
                    uint32_t b0 = W3s[nt * 8 + (lane >> 2)][kt * 8 + (lane & 3)];
                    uint32_t b1 = W3s[nt * 8 + (lane >> 2)][kt * 8 + (lane & 3) + 4];
                    mma16816(d2[0][nt], a[0], b0, b1);
                    mma16816(d2[1][nt], a[1], b0, b1);
                }
            }
            // epi2: relu+b3, accumulate column sums
#pragma unroll
            for (int mt = 0; mt < 2; mt++)
#pragma unroll
                for (int nt = 0; nt < 4; nt++) {
                    acc[nt][0] += fmaxf(d2[mt][nt][0] + b3r[nt][0], 0.f)
                                + fmaxf(d2[mt][nt][2] + b3r[nt][0], 0.f);
                    acc[nt][1] += fmaxf(d2[mt][nt][1] + b3r[nt][1], 0.f)
                                + fmaxf(d2[mt][nt][3] + b3r[nt][1], 0.f);
                }
            mbar_arrive(emptyb);
        }

        // reduce across lanes sharing columns
#pragma unroll
        for (int nt = 0; nt < 4; nt++)
#pragma unroll
            for (int c = 0; c < 2; c++) {
                float v = acc[nt][c];
                v += __shfl_xor_sync(0xFFFFFFFFu, v, 4);
                v += __shfl_xor_sync(0xFFFFFFFFu, v, 8);
                v += __shfl_xor_sync(0xFFFFFFFFu, v, 16);
                acc[nt][c] = v;
            }
        if (lane < 4) {
#pragma unroll
            for (int nt = 0; nt < 4; nt++) {
                wpart[wid][nt * 8 + lane * 2]     = acc[nt][0];
                wpart[wid][nt * 8 + lane * 2 + 1] = acc[nt][1];
            }
        }
    } else {
        // =================== PRODUCER ===================
        int pt = t - 128;   // 0..127
#pragma unroll 1
        for (int tt = 0; tt < 4; tt++) {
            int s = tt & 1;
            uint32_t fullb = s ? full1 : full0;
            uint32_t emptyb = s ? empty1 : empty0;
            if (tt >= 2) mbar_wait(emptyb, 0);
            int i0 = tt * 128;
            Jc[s][pt] = g_Jt[(size_t)j * NN + i0 + pt];
            asm volatile("bar.sync 1, 128;" ::: "memory");   // producer-group barrier
#pragma unroll 4
            for (int q = 0; q < 16; q++) {
                int idx4 = pt + 128 * q;
                int r = idx4 >> 4, c4 = (idx4 & 15) * 4;
                float4 u4 = *(const float4*)(g_u + (i0 + r) * 64 + c4);
                float Jv = Jc[s][r];
                float m0 = fmaxf(fmaf(Jv, wj_s[c4 + 0], u4.x + v_s[c4 + 0]), 0.f);
                float m1 = fmaxf(fmaf(Jv, wj_s[c4 + 1], u4.y + v_s[c4 + 1]), 0.f);
                float m2 = fmaxf(fmaf(Jv, wj_s[c4 + 2], u4.z + v_s[c4 + 2]), 0.f);
                float m3 = fmaxf(fmaf(Jv, wj_s[c4 + 3], u4.w + v_s[c4 + 3]), 0.f);
                *(uint2*)(Atile[s] + SW128(r * 128 + c4 * 2)) =
                    make_uint2(cvt2(m0, m1), cvt2(m2, m3));
            }
            mbar_arrive(fullb);
        }
    }

    __syncthreads();
    if (t < 32)
        g_msum[j * 32 + t] = wpart[0][t] + wpart[1][t] + wpart[2][t] + wpart[3][t];
}

// ---------------- GRU ----------------
__global__ void __launch_bounds__(384) k_gru(const float* __restrict__ Wih,  // (96,64)
                                             const float* __restrict__ Whh,  // (96,32)
                                             const float* __restrict__ bih,
                                             const float* __restrict__ bhh) {
    __shared__ float Wih_s[96][65];
    __shared__ float Whh_s[96][33];
    __shared__ float x_s[4][64];
    __shared__ float gi_s[4][96], gh_s[4][96];
    int t = threadIdx.x;
    int n0 = blockIdx.x * 4;
    for (int idx = t; idx < 96 * 64; idx += 384) Wih_s[idx >> 6][idx & 63] = Wih[idx];
    for (int idx = t; idx < 96 * 32; idx += 384) Whh_s[idx >> 5][idx & 31] = Whh[idx];
    if (t < 256) {
        int nl = t >> 6, c = t & 63;
        x_s[nl][c] = (c < 32) ? g_h[(n0 + nl) * DD + c]
                              : g_msum[(n0 + nl) * DD + (c - 32)];
    }
    __syncthreads();
    int nl = t / 96, q = t % 96;
    float gi = bih[q], gh = bhh[q];
#pragma unroll
    for (int c = 0; c < 64; c++) gi = fmaf(x_s[nl][c], Wih_s[q][c], gi);
#pragma unroll
    for (int c = 0; c < 32; c++) gh = fmaf(x_s[nl][c], Whh_s[q][c], gh);
    gi_s[nl][q] = gi; gh_s[nl][q] = gh;
    __syncthreads();
    if (q < 32) {
        float r  = 1.f / (1.f + expf(-(gi_s[nl][q]      + gh_s[nl][q])));
        float z  = 1.f / (1.f + expf(-(gi_s[nl][32 + q] + gh_s[nl][32 + q])));
        float ng = tanhf(gi_s[nl][64 + q] + r * gh_s[nl][64 + q]);
        g_h[(n0 + nl) * DD + q] = (1.f - z) * ng + z * x_s[nl][q];
    }
}

// ---------------- readout ----------------
__global__ void k_readout(const float* __restrict__ W1, const float* __restrict__ b1,
                          const float* __restrict__ W2, const float* __restrict__ b2,
                          const float* __restrict__ W3, const float* __restrict__ b3,
                          float* __restrict__ out) {
    int jn = blockIdx.x;
    int k = threadIdx.x;                 // 64 threads
    __shared__ float hs[DD], y1[64], y2[64];
    if (k < DD) hs[k] = g_h[jn * DD + k];
    __syncthreads();
    float a = b1[k];
    const float* w1 = W1 + k * DD;
#pragma unroll
    for (int c = 0; c < DD; c++) a = fmaf(hs[c], w1[c], a);
    y1[k] = fmaxf(a, 0.f);
    __syncthreads();
    float a2 = b2[k];
    const float* w2 = W2 + k * 64;
#pragma unroll
    for (int c = 0; c < 64; c++) a2 = fmaf(y1[c], w2[c], a2);
    y2[k] = fmaxf(a2, 0.f);
    __syncthreads();
    if (k < 2) {
        float a3 = b3[k];
        const float* w3 = W3 + k * 64;
#pragma unroll
        for (int c = 0; c < 64; c++) a3 = fmaf(y2[c], w3[c], a3);
        a3 = fmaxf(a3, 0.f);
        out[jn * 2 + k] = 1.f / (1.f + expf(-a3));
    }
}

extern "C" void kernel_launch(void* const* d_in, const int* in_sizes, int n_in,
                              void* d_out, int out_size) {
    const float* J   = (const float*)d_in[0];
    const float* b   = (const float*)d_in[1];
    const float* W1  = (const float*)d_in[2];
    const float* b1  = (const float*)d_in[3];
    const float* W2  = (const float*)d_in[4];
    const float* b2  = (const float*)d_in[5];
    const float* W3  = (const float*)d_in[6];
    const float* b3  = (const float*)d_in[7];
    const float* Wih = (const float*)d_in[8];
    const float* Whh = (const float*)d_in[9];
    const float* bih = (const float*)d_in[10];
    const float* bhh = (const float*)d_in[11];
    const float* rW1 = (const float*)d_in[12];
    const float* rb1 = (const float*)d_in[13];
    const float* rW2 = (const float*)d_in[14];
    const float* rb2 = (const float*)d_in[15];
    const float* rW3 = (const float*)d_in[16];
    const float* rb3 = (const float*)d_in[17];
    float* out = (float*)d_out;

    k_init<<<16, 1024>>>();
    k_tr<<<dim3(16, 16), dim3(32, 8)>>>(J);
    for (int s = 0; s < 5; s++) {
        k_uv<<<64, 256>>>(b, W1, b1);
        k_msg<<<NN, 256>>>(W1, W2, b2, W3, b3);
        k_gru<<<128, 384>>>(Wih, Whh, bih, bhh);
    }
    k_readout<<<NN, 64>>>(rW1, rb1, rW2, rb2, rW3, rb3, out);
}

// round 6
// speedup vs baseline: 5.6262x; 1.0200x over previous
#include <cuda_runtime.h>
#include <math.h>
#include <stdint.h>

#define NN   512
#define DD   32

// ---------------- device scratch ----------------
__device__ float g_h[NN * DD];
__device__ float g_u[NN * 64];
__device__ float g_v[NN * 64];
__device__ float g_msum[NN * DD];
__device__ float g_Jt[NN * NN];

// ---------------- helpers ----------------
static __device__ __forceinline__ uint32_t smem_u32(const void* p) {
    uint32_t a;
    asm("{ .reg .u64 t; cvta.to.shared.u64 t, %1; cvt.u32.u64 %0, t; }"
        : "=r"(a) : "l"(p));
    return a;
}
static __device__ __forceinline__ uint32_t cvt2(float lo, float hi) {
    uint32_t r;
    asm("cvt.rn.bf16x2.f32 %0, %1, %2;" : "=r"(r) : "f"(hi), "f"(lo));
    return r;
}
#define SW128(o) ((o) ^ ((((uint32_t)(o)) >> 3) & 0x70u))

static __device__ __forceinline__ void ldm4(uint32_t* r, uint32_t addr) {
    asm volatile("ldmatrix.sync.aligned.m8n8.x4.shared.b16 {%0,%1,%2,%3},[%4];"
                 : "=r"(r[0]), "=r"(r[1]), "=r"(r[2]), "=r"(r[3]) : "r"(addr));
}
static __device__ __forceinline__ void mma16816(float* d, const uint32_t* a,
                                                uint32_t b0, uint32_t b1) {
    asm volatile(
        "mma.sync.aligned.m16n8k16.row.col.f32.bf16.bf16.f32 "
        "{%0,%1,%2,%3}, {%4,%5,%6,%7}, {%8,%9}, {%0,%1,%2,%3};"
        : "+f"(d[0]), "+f"(d[1]), "+f"(d[2]), "+f"(d[3])
        : "r"(a[0]), "r"(a[1]), "r"(a[2]), "r"(a[3]), "r"(b0), "r"(b1));
}
static __device__ __forceinline__ void mbar_init(uint32_t a, uint32_t cnt) {
    asm volatile("mbarrier.init.shared.b64 [%0], %1;" :: "r"(a), "r"(cnt) : "memory");
}
static __device__ __forceinline__ void mbar_arrive(uint32_t a) {
    asm volatile("mbarrier.arrive.shared.b64 _, [%0];" :: "r"(a) : "memory");
}
static __device__ __forceinline__ void mbar_wait(uint32_t a, uint32_t parity) {
    asm volatile(
        "{\n .reg .pred P;\n"
        "W%=: mbarrier.try_wait.parity.shared.b64 P, [%0], %1;\n"
        " @!P bra W%=;\n}"
        :: "r"(a), "r"(parity) : "memory");
}

// ---------------- init ----------------
__global__ void k_init() {
    int t = blockIdx.x * blockDim.x + threadIdx.x;
    if (t < NN * DD) g_h[t] = 0.f;
}

// ---------------- transpose J ----------------
__global__ void k_tr(const float* __restrict__ J) {
    __shared__ float tile[32][33];
    int bx = blockIdx.x * 32, by = blockIdx.y * 32;
    int tx = threadIdx.x, ty = threadIdx.y;
    for (int yy = ty; yy < 32; yy += 8)
        tile[yy][tx] = J[(by + yy) * NN + bx + tx];
    __syncthreads();
    for (int yy = ty; yy < 32; yy += 8)
        g_Jt[(size_t)(bx + yy) * NN + by + tx] = tile[tx][yy];
}

// ---------------- u/v precompute ----------------
__global__ void __launch_bounds__(256) k_uv(const float* __restrict__ b,
                                            const float* __restrict__ W1,  // (64,67)
                                            const float* __restrict__ b1) {
    __shared__ float W1s[64][69];
    __shared__ float hs[8][32];
    __shared__ float bv[8];
    int t = threadIdx.x;
    int n0 = blockIdx.x * 8;
    for (int idx = t; idx < 64 * 67; idx += 256)
        W1s[idx / 67][idx % 67] = W1[idx];
    {
        int nl = t >> 5, c = t & 31;
        hs[nl][c] = g_h[(n0 + nl) * DD + c];
    }
    if (t < 8) bv[t] = b[n0 + t];
    __syncthreads();
    int k = t & 63;
    int nlb = t >> 6;
    float b1k = b1[k];
#pragma unroll
    for (int rep = 0; rep < 2; rep++) {
        int nl = nlb + rep * 4;
        float uu = bv[nl] * W1s[k][65];
        float vv = bv[nl] * W1s[k][66] + b1k;
#pragma unroll
        for (int d = 0; d < DD; d++) {
            uu = fmaf(hs[nl][d], W1s[k][d], uu);
            vv = fmaf(hs[nl][d], W1s[k][DD + d], vv);
        }
        g_u[(n0 + nl) * 64 + k] = uu;
        g_v[(n0 + nl) * 64 + k] = vv;
    }
}

// ---------------- edge MLP + message sum: warp-specialized, low-reg consumer ----
// 512 blocks (one per j), 256 threads: warps 0-3 consumers, warps 4-7 producers.
// 2-stage smem ring; consumer restructured so only an 8-reg accumulator is
// live per nt-group -> fits 3 blocks/SM.
__global__ void __launch_bounds__(256, 3)
k_msg(const float* __restrict__ W1,
      const float* __restrict__ W2,   // (64,64)
      const float* __restrict__ b2,
      const float* __restrict__ W3,   // (32,64)
      const float* __restrict__ b3) {
    __shared__ uint8_t Atile[2][128 * 128];   // two 128x64 bf16 tiles, SW128
    __shared__ uint32_t W2s[64][36];
    __shared__ uint32_t W3s[32][36];
    __shared__ float v_s[64], wj_s[64], b2_s[64], b3_s[32];
    __shared__ float Jc[2][128];
    __shared__ float wpart[4][32];
    __shared__ __align__(8) unsigned long long mbar_mem[4];

    int t = threadIdx.x;
    int lane = t & 31, wid = t >> 5;
    int j = blockIdx.x;
    uint32_t mb = smem_u32(mbar_mem);
    uint32_t full0 = mb, full1 = mb + 8, empty0 = mb + 16, empty1 = mb + 24;

    for (int idx = t; idx < 2048; idx += 256) {
        int r = idx >> 5, w = idx & 31;
        float2 p = *(const float2*)(W2 + r * 64 + 2 * w);
        W2s[r][w] = cvt2(p.x, p.y);
    }
    for (int idx = t; idx < 1024; idx += 256) {
        int r = idx >> 5, w = idx & 31;
        float2 p = *(const float2*)(W3 + r * 64 + 2 * w);
        W3s[r][w] = cvt2(p.x, p.y);
    }
    if (t < 64) {
        v_s[t]  = g_v[j * 64 + t];
        wj_s[t] = W1[t * 67 + 64];
        b2_s[t] = b2[t];
    }
    if (t < 32) b3_s[t] = b3[t];
    if (t == 0) {
        mbar_init(full0, 128); mbar_init(full1, 128);
        mbar_init(empty0, 128); mbar_init(empty1, 128);
    }
    __syncthreads();

    if (wid < 4) {
        // =================== CONSUMER ===================
        float acc[4][2];
#pragma unroll
        for (int nt = 0; nt < 4; nt++) acc[nt][0] = acc[nt][1] = 0.f;
        int erow = wid * 32 + (lane >> 2);
        int q2 = (lane & 3) * 2;

#pragma unroll 1
        for (int tt = 0; tt < 4; tt++) {
            int s = tt & 1;
            uint32_t fullb = s ? full1 : full0;
            uint32_t emptyb = s ? empty1 : empty0;
            uint32_t abase = smem_u32(Atile[s]);
            mbar_wait(fullb, (tt >> 1) & 1);

            uint32_t a[4][2][4];   // [kt][mt][frag]
#pragma unroll
            for (int kt = 0; kt < 4; kt++)
#pragma unroll
                for (int mt = 0; mt < 2; mt++) {
                    int row = wid * 32 + mt * 16 + (lane & 15);
                    ldm4(a[kt][mt], abase + SW128(row * 128 + kt * 32 + (lane >> 4) * 16));
                }
            // MMA1 + epi1, one nt-group at a time (8-reg accumulator)
#pragma unroll
            for (int nt = 0; nt < 8; nt++) {
                float d[2][4] = {{0.f, 0.f, 0.f, 0.f}, {0.f, 0.f, 0.f, 0.f}};
#pragma unroll
                for (int kt = 0; kt < 4; kt++) {
                    uint32_t b0 = W2s[nt * 8 + (lane >> 2)][kt * 8 + (lane & 3)];
                    uint32_t b1 = W2s[nt * 8 + (lane >> 2)][kt * 8 + (lane & 3) + 4];
                    mma16816(d[0], a[kt][0], b0, b1);
                    mma16816(d[1], a[kt][1], b0, b1);
                }
                float bb0 = b2_s[nt * 8 + q2];
                float bb1 = b2_s[nt * 8 + q2 + 1];
                int cb = (nt * 8 + q2) * 2;
#pragma unroll
                for (int mt = 0; mt < 2; mt++) {
                    int r0 = erow + mt * 16;
                    *(uint32_t*)(Atile[s] + SW128(r0 * 128 + cb)) =
                        cvt2(fmaxf(d[mt][0] + bb0, 0.f), fmaxf(d[mt][1] + bb1, 0.f));
                    *(uint32_t*)(Atile[s] + SW128((r0 + 8) * 128 + cb)) =
                        cvt2(fmaxf(d[mt][2] + bb0, 0.f), fmaxf(d[mt][3] + bb1, 0.f));
                }
            }
            __syncwarp();
            // reload A frags (now m2) and run MMA2 + epi2
#pragma unroll
            for (int kt = 0; kt < 4; kt++)
#pragma unroll
                for (int mt = 0; mt < 2; mt++) {
                    int row = wid * 32 + mt * 16 + (lane & 15);
                    ldm4(a[kt][mt], abase + SW128(row * 128 + kt * 32 + (lane >> 4) * 16));
                }
#pragma unroll
            for (int nt = 0; nt < 4; nt++) {
                float d[2][4] = {{0.f, 0.f, 0.f, 0.f}, {0.f, 0.f, 0.f, 0.f}};
#pragma unroll
                for (int kt = 0; kt < 4; kt++) {
                    uint32_t b0 = W3s[nt * 8 + (lane >> 2)][kt * 8 + (lane & 3)];
                    uint32_t b1 = W3s[nt * 8 + (lane >> 2)][kt * 8 + (lane & 3) + 4];
                    mma16816(d[0], a[kt][0], b0, b1);
                    mma16816(d[1], a[kt][1], b0, b1);
                }
                float bb0 = b3_s[nt * 8 + q2];
                float bb1 = b3_s[nt * 8 + q2 + 1];
                acc[nt][0] += fmaxf(d[0][0] + bb0, 0.f) + fmaxf(d[0][2] + bb0, 0.f)
                            + fmaxf(d[1][0] + bb0, 0.f) + fmaxf(d[1][2] + bb0, 0.f);
                acc[nt][1] += fmaxf(d[0][1] + bb1, 0.f) + fmaxf(d[0][3] + bb1, 0.f)
                            + fmaxf(d[1][1] + bb1, 0.f) + fmaxf(d[1][3] + bb1, 0.f);
            }
            mbar_arrive(emptyb);
        }

        // reduce across lanes sharing columns
#pragma unroll
        for (int nt = 0; nt < 4; nt++)
#pragma unroll
            for (int c = 0; c < 2; c++) {
                float v = acc[nt][c];
                v += __shfl_xor_sync(0xFFFFFFFFu, v, 4);
                v += __shfl_xor_sync(0xFFFFFFFFu, v, 8);
                v += __shfl_xor_sync(0xFFFFFFFFu, v, 16);
                acc[nt][c] = v;
            }
        if (lane < 4) {
#pragma unroll
            for (int nt = 0; nt < 4; nt++) {
                wpart[wid][nt * 8 + lane * 2]     = acc[nt][0];
                wpart[wid][nt * 8 + lane * 2 + 1] = acc[nt][1];
            }
        }
    } else {
        // =================== PRODUCER ===================
        int pt = t - 128;
#pragma unroll 1
        for (int tt = 0; tt < 4; tt++) {
            int s = tt & 1;
            uint32_t fullb = s ? full1 : full0;
            uint32_t emptyb = s ? empty1 : empty0;
            if (tt >= 2) mbar_wait(emptyb, 0);
            int i0 = tt * 128;
            Jc[s][pt] = g_Jt[(size_t)j * NN + i0 + pt];
            asm volatile("bar.sync 1, 128;" ::: "memory");
#pragma unroll 4
            for (int q = 0; q < 16; q++) {
                int idx4 = pt + 128 * q;
                int r = idx4 >> 4, c4 = (idx4 & 15) * 4;
                float4 u4 = *(const float4*)(g_u + (i0 + r) * 64 + c4);
                float Jv = Jc[s][r];
                float m0 = fmaxf(fmaf(Jv, wj_s[c4 + 0], u4.x + v_s[c4 + 0]), 0.f);
                float m1 = fmaxf(fmaf(Jv, wj_s[c4 + 1], u4.y + v_s[c4 + 1]), 0.f);
                float m2 = fmaxf(fmaf(Jv, wj_s[c4 + 2], u4.z + v_s[c4 + 2]), 0.f);
                float m3 = fmaxf(fmaf(Jv, wj_s[c4 + 3], u4.w + v_s[c4 + 3]), 0.f);
                *(uint2*)(Atile[s] + SW128(r * 128 + c4 * 2)) =
                    make_uint2(cvt2(m0, m1), cvt2(m2, m3));
            }
            mbar_arrive(fullb);
        }
    }

    __syncthreads();
    if (t < 32)
        g_msum[j * 32 + t] = wpart[0][t] + wpart[1][t] + wpart[2][t] + wpart[3][t];
}

// ---------------- GRU ----------------
__global__ void __launch_bounds__(384) k_gru(const float* __restrict__ Wih,  // (96,64)
                                             const float* __restrict__ Whh,  // (96,32)
                                             const float* __restrict__ bih,
                                             const float* __restrict__ bhh) {
    __shared__ float Wih_s[96][65];
    __shared__ float Whh_s[96][33];
    __shared__ float x_s[4][64];
    __shared__ float gi_s[4][96], gh_s[4][96];
    int t = threadIdx.x;
    int n0 = blockIdx.x * 4;
    for (int idx = t; idx < 96 * 64; idx += 384) Wih_s[idx >> 6][idx & 63] = Wih[idx];
    for (int idx = t; idx < 96 * 32; idx += 384) Whh_s[idx >> 5][idx & 31] = Whh[idx];
    if (t < 256) {
        int nl = t >> 6, c = t & 63;
        x_s[nl][c] = (c < 32) ? g_h[(n0 + nl) * DD + c]
                              : g_msum[(n0 + nl) * DD + (c - 32)];
    }
    __syncthreads();
    int nl = t / 96, q = t % 96;
    float gi = bih[q], gh = bhh[q];
#pragma unroll
    for (int c = 0; c < 64; c++) gi = fmaf(x_s[nl][c], Wih_s[q][c], gi);
#pragma unroll
    for (int c = 0; c < 32; c++) gh = fmaf(x_s[nl][c], Whh_s[q][c], gh);
    gi_s[nl][q] = gi; gh_s[nl][q] = gh;
    __syncthreads();
    if (q < 32) {
        float r  = 1.f / (1.f + expf(-(gi_s[nl][q]      + gh_s[nl][q])));
        float z  = 1.f / (1.f + expf(-(gi_s[nl][32 + q] + gh_s[nl][32 + q])));
        float ng = tanhf(gi_s[nl][64 + q] + r * gh_s[nl][64 + q]);
        g_h[(n0 + nl) * DD + q] = (1.f - z) * ng + z * x_s[nl][q];
    }
}

// ---------------- readout ----------------
__global__ void k_readout(const float* __restrict__ W1, const float* __restrict__ b1,
                          const float* __restrict__ W2, const float* __restrict__ b2,
                          const float* __restrict__ W3, const float* __restrict__ b3,
                          float* __restrict__ out) {
    int jn = blockIdx.x;
    int k = threadIdx.x;                 // 64 threads
    __shared__ float hs[DD], y1[64], y2[64];
    if (k < DD) hs[k] = g_h[jn * DD + k];
    __syncthreads();
    float a = b1[k];
    const float* w1 = W1 + k * DD;
#pragma unroll
    for (int c = 0; c < DD; c++) a = fmaf(hs[c], w1[c], a);
    y1[k] = fmaxf(a, 0.f);
    __syncthreads();
    float a2 = b2[k];
    const float* w2 = W2 + k * 64;
#pragma unroll
    for (int c = 0; c < 64; c++) a2 = fmaf(y1[c], w2[c], a2);
    y2[k] = fmaxf(a2, 0.f);
    __syncthreads();
    if (k < 2) {
        float a3 = b3[k];
        const float* w3 = W3 + k * 64;
#pragma unroll
        for (int c = 0; c < 64; c++) a3 = fmaf(y2[c], w3[c], a3);
        a3 = fmaxf(a3, 0.f);
        out[jn * 2 + k] = 1.f / (1.f + expf(-a3));
    }
}

extern "C" void kernel_launch(void* const* d_in, const int* in_sizes, int n_in,
                              void* d_out, int out_size) {
    const float* J   = (const float*)d_in[0];
    const float* b   = (const float*)d_in[1];
    const float* W1  = (const float*)d_in[2];
    const float* b1  = (const float*)d_in[3];
    const float* W2  = (const float*)d_in[4];
    const float* b2  = (const float*)d_in[5];
    const float* W3  = (const float*)d_in[6];
    const float* b3  = (const float*)d_in[7];
    const float* Wih = (const float*)d_in[8];
    const float* Whh = (const float*)d_in[9];
    const float* bih = (const float*)d_in[10];
    const float* bhh = (const float*)d_in[11];
    const float* rW1 = (const float*)d_in[12];
    const float* rb1 = (const float*)d_in[13];
    const float* rW2 = (const float*)d_in[14];
    const float* rb2 = (const float*)d_in[15];
    const float* rW3 = (const float*)d_in[16];
    const float* rb3 = (const float*)d_in[17];
    float* out = (float*)d_out;

    k_init<<<16, 1024>>>();
    k_tr<<<dim3(16, 16), dim3(32, 8)>>>(J);
    for (int s = 0; s < 5; s++) {
        k_uv<<<64, 256>>>(b, W1, b1);
        k_msg<<<NN, 256>>>(W1, W2, b2, W3, b3);
        k_gru<<<128, 384>>>(Wih, Whh, bih, bhh);
    }
    k_readout<<<NN, 64>>>(rW1, rb1, rW2, rb2, rW3, rb3, out);
}